// round 13
// baseline (speedup 1.0000x reference)
#include <cuda_runtime.h>
#include <cstdint>

#define MN       1024
#define BATCH    2048
#define DIM      128
#define NITER_F  100.0f
#define ALPHA_F  0.3f
#define SIGMA_F  16.0f

// ---------------- scratch ----------------
__device__ unsigned long long g_part[16][BATCH]; // per-cell-block argmin partials
__device__ float g_S[MN * DIM];
__device__ float g_cnt[MN];

__device__ __forceinline__ unsigned int f2ord(float f) {
    unsigned int u = __float_as_uint(f);
    return (u & 0x80000000u) ? ~u : (u | 0x80000000u);
}

__device__ __forceinline__ float tf32_rna(float v) {
    uint32_t u;
    asm("cvt.rna.tf32.f32 %0, %1;" : "=r"(u) : "f"(v));
    return __uint_as_float(u);
}

__device__ __forceinline__ void mma_tf32(float* d, const uint32_t* a,
                                         uint32_t b0, uint32_t b1) {
    asm volatile(
        "mma.sync.aligned.m16n8k8.row.col.f32.tf32.tf32.f32 "
        "{%0,%1,%2,%3}, {%4,%5,%6,%7}, {%8,%9}, {%0,%1,%2,%3};"
        : "+f"(d[0]), "+f"(d[1]), "+f"(d[2]), "+f"(d[3])
        : "r"(a[0]), "r"(a[1]), "r"(a[2]), "r"(a[3]), "r"(b0), "r"(b1));
}

// smem tile geometry: rows x 64 k (pair-interleaved), row stride 72 floats
// (72 mod 32 == 8 -> fragment LDS.64 across 8 rows is bank-conflict-free)
#define TSTR 72
#define XTILE_F (128 * TSTR)     // X: 128 batch rows
#define WTILE_F (64 * TSTR)      // W: 64 cell rows

#define OFF_XHI 0
#define OFF_XLO (OFF_XHI + XTILE_F)
#define OFF_WHI (OFF_XLO + XTILE_F)
#define OFF_WLO (OFF_WHI + WTILE_F)
#define OFF_W2S (OFF_WLO + WTILE_F)
#define BMU_SMEM_F (OFF_W2S + 64)

// ---------------- K1: BMU GEMM via mma.sync tf32 (fused 3-term) ------------
// block: 128 batch rows x 64 cells, 4 warps, each 32 batch rows (2 m16 tiles)
// x 64 cells. 2 CTAs/SM (2 x 110.8KB smem). Fused term loading: per k-step a
// warp does 24 LDS.64 for 48 MMAs (vs 30/24 in the 3-pass version).
// k layout within a group of 8: pos = 2*(k&3) + (k>>2) -> fragment = LDS.64.
__global__ __launch_bounds__(128, 2)
void k_bmu(const float* __restrict__ x, const float* __restrict__ w) {
    extern __shared__ float smem[];
    float* w2s = smem + OFF_W2S;         // [64]

    const int tid  = threadIdx.x;
    const int wrp  = tid >> 5;           // 0..3
    const int lane = tid & 31;
    const int gid  = lane >> 2;          // group id 0..7
    const int tig  = lane & 3;           // thread in group
    const int b0 = blockIdx.x * 128;     // batch tile
    const int m0 = blockIdx.y * 64;      // cell tile

    // fold scratch zeroing into this kernel: 256 blocks x 512 floats = all g_S
    {
        int z = blockIdx.y * 16 + blockIdx.x;            // 0..255
        *(float4*)&g_S[z * 512 + tid * 4] = make_float4(0.f, 0.f, 0.f, 0.f);
        if (tid == 127)
            *(float4*)&g_cnt[z * 4] = make_float4(0.f, 0.f, 0.f, 0.f);
    }

    // w2 for this block's 64 cells (L2-resident)
    if (tid < 64) {
        float s = 0.0f;
        #pragma unroll
        for (int g = 0; g < 32; g++) {
            float4 v = *(const float4*)&w[(m0 + tid) * DIM + g * 4];
            s += v.x * v.x + v.y * v.y + v.z * v.z + v.w * v.w;
        }
        w2s[tid] = s;
    }

    // acc[mt][t][4] : mt = m16 tile (rows wrp*32 + mt*16 + ...), t = n8 tile
    float acc[2][8][4];
    #pragma unroll
    for (int mt = 0; mt < 2; mt++)
        #pragma unroll
        for (int t = 0; t < 8; t++)
            #pragma unroll
            for (int j = 0; j < 4; j++) acc[mt][t][j] = 0.0f;

    #pragma unroll 1
    for (int c = 0; c < 2; c++) {
        const int kc = c * 64;
        if (c) __syncthreads();   // protect tiles while prior mma reads

        // stage X chunk: 128 rows x 16 q -> 2048 float4s, 16 per thread
        #pragma unroll
        for (int i = 0; i < 16; i++) {
            int idx = tid + i * 128;
            int row = idx >> 4;
            int q   = idx & 15;
            int base = row * TSTR + (q >> 1) * 8 + (q & 1);
            float4 xv = *(const float4*)&x[(b0 + row) * DIM + kc + q * 4];
            float h;
            h = tf32_rna(xv.x); smem[OFF_XHI + base + 0] = h; smem[OFF_XLO + base + 0] = tf32_rna(xv.x - h);
            h = tf32_rna(xv.y); smem[OFF_XHI + base + 2] = h; smem[OFF_XLO + base + 2] = tf32_rna(xv.y - h);
            h = tf32_rna(xv.z); smem[OFF_XHI + base + 4] = h; smem[OFF_XLO + base + 4] = tf32_rna(xv.z - h);
            h = tf32_rna(xv.w); smem[OFF_XHI + base + 6] = h; smem[OFF_XLO + base + 6] = tf32_rna(xv.w - h);
        }
        // stage W chunk: 64 rows x 16 q -> 1024 float4s, 8 per thread
        #pragma unroll
        for (int i = 0; i < 8; i++) {
            int idx = tid + i * 128;
            int row = idx >> 4;
            int q   = idx & 15;
            int base = row * TSTR + (q >> 1) * 8 + (q & 1);
            float4 wv = *(const float4*)&w[(m0 + row) * DIM + kc + q * 4];
            float h;
            h = tf32_rna(wv.x); smem[OFF_WHI + base + 0] = h; smem[OFF_WLO + base + 0] = tf32_rna(wv.x - h);
            h = tf32_rna(wv.y); smem[OFF_WHI + base + 2] = h; smem[OFF_WLO + base + 2] = tf32_rna(wv.y - h);
            h = tf32_rna(wv.z); smem[OFF_WHI + base + 4] = h; smem[OFF_WLO + base + 4] = tf32_rna(wv.z - h);
            h = tf32_rna(wv.w); smem[OFF_WHI + base + 6] = h; smem[OFF_WLO + base + 6] = tf32_rna(wv.w - h);
        }
        __syncthreads();

        // fused 3-term mainloop: per k-step load A(hi,lo) for 2 m-tiles once,
        // then per t: B(hi,lo) once -> 6 MMAs (hihi, hilo, lohi for each mt)
        #pragma unroll
        for (int g = 0; g < 8; g++) {
            uint32_t ah[2][4], al[2][4];
            #pragma unroll
            for (int mt = 0; mt < 2; mt++) {
                const int apos = (wrp * 32 + mt * 16 + gid) * TSTR + g * 8 + tig * 2;
                float2 h0 = *(const float2*)&smem[OFF_XHI + apos];
                float2 h1 = *(const float2*)&smem[OFF_XHI + apos + 8 * TSTR];
                float2 l0 = *(const float2*)&smem[OFF_XLO + apos];
                float2 l1 = *(const float2*)&smem[OFF_XLO + apos + 8 * TSTR];
                ah[mt][0] = __float_as_uint(h0.x); ah[mt][1] = __float_as_uint(h1.x);
                ah[mt][2] = __float_as_uint(h0.y); ah[mt][3] = __float_as_uint(h1.y);
                al[mt][0] = __float_as_uint(l0.x); al[mt][1] = __float_as_uint(l1.x);
                al[mt][2] = __float_as_uint(l0.y); al[mt][3] = __float_as_uint(l1.y);
            }
            #pragma unroll
            for (int t = 0; t < 8; t++) {
                const int bpos = (t * 8 + gid) * TSTR + g * 8 + tig * 2;
                float2 bh = *(const float2*)&smem[OFF_WHI + bpos];
                float2 bl = *(const float2*)&smem[OFF_WLO + bpos];
                uint32_t bh0 = __float_as_uint(bh.x), bh1 = __float_as_uint(bh.y);
                uint32_t bl0 = __float_as_uint(bl.x), bl1 = __float_as_uint(bl.y);
                mma_tf32(acc[0][t], ah[0], bh0, bh1);   // hi*hi
                mma_tf32(acc[1][t], ah[1], bh0, bh1);
                mma_tf32(acc[0][t], ah[0], bl0, bl1);   // hi*lo
                mma_tf32(acc[1][t], ah[1], bl0, bl1);
                mma_tf32(acc[0][t], al[0], bh0, bh1);   // lo*hi
                mma_tf32(acc[1][t], al[1], bh0, bh1);
            }
        }
    }

    // epilogue: rows = batch, cols = cells -> per-thread argmin over 16 cols,
    // quad shuffle-min, lane tig==0 writes the row result.
    #pragma unroll
    for (int mt = 0; mt < 2; mt++) {
        #pragma unroll
        for (int rp = 0; rp < 2; rp++) {   // row = gid, gid+8 within m-tile
            unsigned long long best = 0xFFFFFFFFFFFFFFFFULL;
            #pragma unroll
            for (int t = 0; t < 8; t++) {
                int c0 = t * 8 + tig * 2;
                float d2a = w2s[c0]     - 2.0f * acc[mt][t][rp * 2 + 0];
                float d2b = w2s[c0 + 1] - 2.0f * acc[mt][t][rp * 2 + 1];
                unsigned long long ka = ((unsigned long long)f2ord(d2a) << 32)
                                      | (unsigned long long)(m0 + c0);
                unsigned long long kb = ((unsigned long long)f2ord(d2b) << 32)
                                      | (unsigned long long)(m0 + c0 + 1);
                best = min(best, min(ka, kb));
            }
            best = min(best, __shfl_xor_sync(0xffffffffu, best, 1));
            best = min(best, __shfl_xor_sync(0xffffffffu, best, 2));
            if (tig == 0) {
                int row = wrp * 32 + mt * 16 + rp * 8 + gid;
                g_part[blockIdx.y][b0 + row] = best;
            }
        }
    }
}

// ---------------- K2: reduce partials + scatter x rows into BMU bins --------
__global__ void k_scatter(const float* __restrict__ x) {
    int warp = (blockIdx.x * blockDim.x + threadIdx.x) >> 5;  // 0..2047
    int lane = threadIdx.x & 31;
    if (warp >= BATCH) return;

    unsigned long long v = (lane < 16) ? g_part[lane][warp]
                                       : 0xFFFFFFFFFFFFFFFFULL;
    #pragma unroll
    for (int o = 8; o >= 1; o >>= 1)
        v = min(v, __shfl_xor_sync(0xffffffffu, v, o));
    v = __shfl_sync(0xffffffffu, v, 0);
    int m = (int)(v & 0xFFFFFFFFULL);

    float4 vv = *(const float4*)&x[warp * DIM + lane * 4];
    float* dst = &g_S[m * DIM + lane * 4];
    asm volatile("red.global.add.v4.f32 [%0], {%1, %2, %3, %4};"
                 :: "l"(dst), "f"(vv.x), "f"(vv.y), "f"(vv.z), "f"(vv.w)
                 : "memory");
    if (lane == 0) atomicAdd(&g_cnt[m], 1.0f);
}

// ---------------- K3: fused separable gaussian contraction + update ---------
// 128 blocks = (cx, d-quarter), 256 threads.
__global__ __launch_bounds__(256)
void k_tail(const float* __restrict__ w,
            const int* __restrict__ it,
            float* __restrict__ out) {
    __shared__ float4 Ts[32][9];     // [by][dq], padded
    __shared__ float tc_s[32];
    __shared__ float e_s[32];

    const int cx = blockIdx.x & 31;
    const int d0 = (blockIdx.x >> 5) * 32;   // d-quarter base
    const int tid = threadIdx.x;

    float lr_decay = 1.0f - (float)it[0] / NITER_F;
    float alpha_op = ALPHA_F * lr_decay;
    float sig = SIGMA_F * lr_decay;
    float inv_s2 = 1.0f / (sig * sig);

    if (tid < 32) e_s[tid] = expf(-(float)(tid * tid) * inv_s2);
    __syncthreads();

    // stage A: Ts[by][d] = sum_bx e(|cx-bx|) * S[by*32+bx][d]
    {
        const int by = tid >> 3;           // 0..31
        const int dq = tid & 7;            // float4 index
        const int d  = d0 + dq * 4;
        float4 a = make_float4(0.f, 0.f, 0.f, 0.f);
        #pragma unroll
        for (int bb = 0; bb < 4; bb++) {
            float4 sv[8];
            #pragma unroll
            for (int j = 0; j < 8; j++)
                sv[j] = *(const float4*)&g_S[(by * 32 + bb * 8 + j) * DIM + d];
            #pragma unroll
            for (int j = 0; j < 8; j++) {
                float e = e_s[abs(cx - (bb * 8 + j))];
                a.x += e * sv[j].x; a.y += e * sv[j].y;
                a.z += e * sv[j].z; a.w += e * sv[j].w;
            }
        }
        Ts[by][dq] = a;
    }
    if (tid < 32) {
        float c = 0.0f;
        #pragma unroll
        for (int bx = 0; bx < 32; bx++)
            c += e_s[abs(cx - bx)] * g_cnt[tid * 32 + bx];
        tc_s[tid] = c;
    }
    __syncthreads();

    // stage B
    {
        const int cy = tid >> 3;
        const int dq = tid & 7;
        const int d  = d0 + dq * 4;
        float4 a = make_float4(0.f, 0.f, 0.f, 0.f);
        float s = 0.0f;
        #pragma unroll
        for (int by = 0; by < 32; by++) {
            float e = e_s[abs(cy - by)];
            float4 t = Ts[by][dq];
            a.x += e * t.x; a.y += e * t.y;
            a.z += e * t.z; a.w += e * t.w;
            s += e * tc_s[by];
        }
        const int c = (cy * 32 + cx) * DIM + d;
        float4 wv = *(const float4*)&w[c];
        float4 o;
        o.x = wv.x + alpha_op * (a.x - s * wv.x);
        o.y = wv.y + alpha_op * (a.y - s * wv.y);
        o.z = wv.z + alpha_op * (a.z - s * wv.z);
        o.w = wv.w + alpha_op * (a.w - s * wv.w);
        *(float4*)&out[c] = o;
    }
}

// ---------------- launch ----------------
extern "C" void kernel_launch(void* const* d_in, const int* in_sizes, int n_in,
                              void* d_out, int out_size) {
    const float* x   = (const float*)d_in[0];   // [2048,128]
    const float* w   = (const float*)d_in[1];   // [1024,128]
    const int*   it  = (const int*)d_in[3];
    float* out = (float*)d_out;

    const int bmu_smem = BMU_SMEM_F * 4;   // ~110.8KB
    cudaFuncSetAttribute(k_bmu, cudaFuncAttributeMaxDynamicSharedMemorySize,
                         bmu_smem);

    k_bmu<<<dim3(16, 16), 128, bmu_smem>>>(x, w);
    k_scatter<<<256, 256>>>(x);
    k_tail<<<128, 256>>>(w, it, out);
}